// round 5
// baseline (speedup 1.0000x reference)
#include <cuda_runtime.h>

#define TT    8192
#define SEG   2048
#define HALO  256
#define TOT   (SEG + HALO)     // 2304
#define NTH   256
#define CH    8                // emission chunk
#define CHS   9                // scan chunk (TOT/NTH)
#define NW    (NTH/32)
#define FEPS  1e-8f
#define SC_SZ (TOT + TOT/32)   // 2376

__device__ __forceinline__ int PADI(int i){ return i + (i >> 5); }

// inclusive warp scan of affine states: (c,d) == y_out = c*y_in + d
__device__ __forceinline__ void wscan(float& c, float& d, int lane){
    #pragma unroll
    for (int off = 1; off < 32; off <<= 1) {
        float pc = __shfl_up_sync(0xffffffffu, c, off);
        float pd = __shfl_up_sync(0xffffffffu, d, off);
        if (lane >= off) { d = fmaf(pd, c, d); c *= pc; }
    }
}

extern "C" __global__ void __launch_bounds__(NTH, 4)
feat_kernel(const float* __restrict__ gclose, float* __restrict__ gout, size_t BT)
{
    __shared__ float sc[SC_SZ];
    __shared__ float SS[TOT / CH];          // 288 8-chunk sums (halo 0..31, seg 32..287)
    __shared__ float swp[3 * NW];
    __shared__ float si[3 * NTH];

    const int blk  = blockIdx.x;
    const int row  = blk >> 2;
    const int seg  = blk & 3;
    const int tid  = threadIdx.x;
    const int lane = tid & 31;
    const int wid  = tid >> 5;
    const float* x = gclose + (size_t)row * TT;
    const int basem = seg * SEG;

    // ---- fill smem [basem-HALO, basem+SEG), left-pad with x[0] ----
    {
        const float x0 = x[0];
        #pragma unroll
        for (int j = 0; j < 3; ++j) {
            int i4 = tid + j * NTH;
            if (i4 < TOT / 4) {
                int gi = basem - HALO + i4 * 4;
                float4 v = (gi >= 0) ? *(const float4*)(x + gi)
                                     : make_float4(x0, x0, x0, x0);
                int b = i4 * 4;
                sc[PADI(b)]     = v.x;
                sc[PADI(b + 1)] = v.y;
                sc[PADI(b + 2)] = v.z;
                sc[PADI(b + 3)] = v.w;
            }
        }
    }
    __syncthreads();

    const float aF = 2.0f / 13.0f, omF = 1.0f - aF;
    const float aS = 2.0f / 27.0f, omS = 1.0f - aS;
    const float aG = 0.2f,         omG = 0.8f;

    const int i0 = HALO + CH * tid;         // first emitted smem index (8-aligned)
    const int ct = 32 + tid;                // my emission chunk id in SS
    float* ob = gout + (size_t)row * TT + basem + CH * tid;

    // ===== pass A: EMA12/26 affine scan over TOT (CHS=9/thread) + SS fill =====
    float yF0, yS0;
    {
        const int s0 = tid * CHS;
        float cF = 1.f, dF = 0.f, cS = 1.f, dS = 0.f;
        #pragma unroll
        for (int k = 0; k < CHS; ++k) {
            float v = sc[PADI(s0 + k)];
            dF = fmaf(aF, v, omF * dF); cF *= omF;
            dS = fmaf(aS, v, omS * dS); cS *= omS;
        }
        // emission-aligned chunk sums (SS) — written before this pass's barrier
        {
            float S = 0.f;
            #pragma unroll
            for (int k = 0; k < CH; ++k) S += sc[PADI(i0 + k)];
            SS[ct] = S;
            if (tid < 32) {
                float sh = 0.f;
                #pragma unroll
                for (int k = 0; k < CH; ++k) sh += sc[PADI(tid * CH + k)];
                SS[tid] = sh;
            }
        }
        wscan(cF, dF, lane);
        wscan(cS, dS, lane);
        if (lane == 31) { swp[wid] = dF; swp[NW + wid] = dS; }
        float uF  = __shfl_up_sync(0xffffffffu, dF, 1);
        float ucF = __shfl_up_sync(0xffffffffu, cF, 1);
        float uS  = __shfl_up_sync(0xffffffffu, dS, 1);
        float ucS = __shfl_up_sync(0xffffffffu, cS, 1);
        __syncthreads();
        // per-warp decay om^288 < 3e-10 -> previous warp's aggregate suffices
        float pF = (wid > 0) ? swp[wid - 1]      : 0.f;
        float pS = (wid > 0) ? swp[NW + wid - 1] : 0.f;
        yF0 = (lane == 0) ? pF : fmaf(ucF, pF, uF);
        yS0 = (lane == 0) ? pS : fmaf(ucS, pS, uS);
    }

    // ===== pass B: EMA9 over macd (replay from yF0/yS0) =====
    float y90;
    {
        const int s0 = tid * CHS;
        float yF = yF0, yS = yS0, cG = 1.f, dG = 0.f;
        #pragma unroll
        for (int k = 0; k < CHS; ++k) {
            float v = sc[PADI(s0 + k)];
            yF = fmaf(aF, v, omF * yF);
            yS = fmaf(aS, v, omS * yS);
            float m = yF - yS;
            dG = fmaf(aG, m, omG * dG); cG *= omG;
        }
        wscan(cG, dG, lane);
        if (lane == 31) swp[2 * NW + wid] = dG;
        float uG  = __shfl_up_sync(0xffffffffu, dG, 1);
        float ucG = __shfl_up_sync(0xffffffffu, cG, 1);
        __syncthreads();
        float pG = (wid > 0) ? swp[2 * NW + wid - 1] : 0.f;
        y90 = (lane == 0) ? pG : fmaf(ucG, pG, uG);
    }
    si[tid] = yF0; si[NTH + tid] = yS0; si[2 * NTH + tid] = y90;
    __syncthreads();

    // ===== phase C: emit macd(9), signal(10), hist(11) =====
    {
        int c = i0 / CHS;
        int r = i0 - c * CHS;               // 0..8 replay
        float yF = si[c], yS = si[NTH + c], y9 = si[2 * NTH + c];
        int p = c * CHS;
        #pragma unroll 1
        for (int k = 0; k < 9; ++k) {
            if (k >= r) break;
            float v = sc[PADI(p + k)];
            yF = fmaf(aF, v, omF * yF);
            yS = fmaf(aS, v, omS * yS);
            float m = yF - yS;
            y9 = fmaf(aG, m, omG * y9);
        }
        float* om9 = ob + 9  * BT;
        float* osg = ob + 10 * BT;
        float* oh  = ob + 11 * BT;
        #pragma unroll
        for (int g = 0; g < CH / 4; ++g) {
            float mb[4], sb[4], hb[4];
            #pragma unroll
            for (int jj = 0; jj < 4; ++jj) {
                float v = sc[PADI(i0 + g * 4 + jj)];
                yF = fmaf(aF, v, omF * yF);
                yS = fmaf(aS, v, omS * yS);
                float m = yF - yS;
                y9 = fmaf(aG, m, omG * y9);
                mb[jj] = m; sb[jj] = y9; hb[jj] = m - y9;
            }
            *(float4*)(om9 + g * 4) = make_float4(mb[0], mb[1], mb[2], mb[3]);
            *(float4*)(osg + g * 4) = make_float4(sb[0], sb[1], sb[2], sb[3]);
            *(float4*)(oh  + g * 4) = make_float4(hb[0], hb[1], hb[2], hb[3]);
        }
    }

    // ===== phase W: MA5/10/20/50 + ratios (0..7), RSI (8), ATR (16) =====
    float wdB;   // 20-sum ending i0-21 (for Bollinger)
    {
        float L[16];
        #pragma unroll
        for (int k = 1; k <= 15; ++k) L[k] = sc[PADI(i0 - k)];
        float s5  = L[1] + L[2] + L[3] + L[4] + L[5];
        float s10 = SS[ct - 1] + L[9] + L[10];
        float s20 = SS[ct - 1] + SS[ct - 2]
                  + sc[PADI(i0 - 17)] + sc[PADI(i0 - 18)] + sc[PADI(i0 - 19)] + sc[PADI(i0 - 20)];
        float s50 = SS[ct - 1] + SS[ct - 2] + SS[ct - 3] + SS[ct - 4] + SS[ct - 5] + SS[ct - 6]
                  + sc[PADI(i0 - 49)] + sc[PADI(i0 - 50)];
        wdB = SS[ct - 5] + SS[ct - 4]
            + sc[PADI(i0 - 21)] + sc[PADI(i0 - 22)] + sc[PADI(i0 - 23)] + sc[PADI(i0 - 24)];
        float gs = 0.f, ls = 0.f;
        #pragma unroll
        for (int k = 1; k <= 14; ++k) {
            float d = L[k] - L[k + 1];
            gs += fmaxf(d, 0.f);
            ls += fmaxf(-d, 0.f);
        }
        float xprev = L[1];
        float xm15  = L[15];
        #pragma unroll
        for (int g = 0; g < CH / 4; ++g) {
            float a0[4], a1[4], a2[4], a3[4], a4[4], a5v[4], a6[4], a7[4], a8[4], a9[4];
            #pragma unroll
            for (int jj = 0; jj < 4; ++jj) {
                int ii = i0 + g * 4 + jj;
                float xt = sc[PADI(ii)];
                s5  += xt - sc[PADI(ii - 5)];
                s10 += xt - sc[PADI(ii - 10)];
                s20 += xt - sc[PADI(ii - 20)];
                s50 += xt - sc[PADI(ii - 50)];
                float d = xt - xprev;
                gs += fmaxf(d, 0.f);
                ls += fmaxf(-d, 0.f);
                float xm14 = sc[PADI(ii - 14)];
                float dl = xm14 - xm15;
                gs -= fmaxf(dl, 0.f);
                ls -= fmaxf(-dl, 0.f);
                xm15 = xm14; xprev = xt;
                float ma5  = s5  * 0.2f;
                float ma10 = s10 * 0.1f;
                float ma20 = s20 * 0.05f;
                float ma50 = s50 * 0.02f;
                a0[jj] = ma5;  a1[jj]  = __fdividef(xt, ma5  + FEPS);
                a2[jj] = ma10; a3[jj]  = __fdividef(xt, ma10 + FEPS);
                a4[jj] = ma20; a5v[jj] = __fdividef(xt, ma20 + FEPS);
                a6[jj] = ma50; a7[jj]  = __fdividef(xt, ma50 + FEPS);
                a8[jj] = 100.f * __fdividef(gs, gs + ls + 14.f * FEPS);
                a9[jj] = (gs + ls) * (1.f / 14.f);
            }
            int go = g * 4;
            *(float4*)(ob + 0  * BT + go) = make_float4(a0[0], a0[1], a0[2], a0[3]);
            *(float4*)(ob + 1  * BT + go) = make_float4(a1[0], a1[1], a1[2], a1[3]);
            *(float4*)(ob + 2  * BT + go) = make_float4(a2[0], a2[1], a2[2], a2[3]);
            *(float4*)(ob + 3  * BT + go) = make_float4(a3[0], a3[1], a3[2], a3[3]);
            *(float4*)(ob + 4  * BT + go) = make_float4(a4[0], a4[1], a4[2], a4[3]);
            *(float4*)(ob + 5  * BT + go) = make_float4(a5v[0], a5v[1], a5v[2], a5v[3]);
            *(float4*)(ob + 6  * BT + go) = make_float4(a6[0], a6[1], a6[2], a6[3]);
            *(float4*)(ob + 7  * BT + go) = make_float4(a7[0], a7[1], a7[2], a7[3]);
            *(float4*)(ob + 8  * BT + go) = make_float4(a8[0], a8[1], a8[2], a8[3]);
            *(float4*)(ob + 16 * BT + go) = make_float4(a9[0], a9[1], a9[2], a9[3]);
        }
    }

    // ===== phase BB: Bollinger (12,13,14) + %B (15), sliding Σ(x−ma)² =====
    {
        float w = wdB;              // 20-sum ending i0-21
        float V = 0.f;
        #pragma unroll 1
        for (int j = i0 - 20; j <= i0 - 1; ++j) {
            float xv = sc[PADI(j)];
            w += xv - sc[PADI(j - 20)];          // w ends at j
            float ma = w * 0.05f;
            float t = xv - ma;
            V = fmaf(t, t, V);
        }
        float wd = wdB;             // delayed 20-sum tracker
        #pragma unroll
        for (int g = 0; g < CH / 4; ++g) {
            float b0[4], b1[4], b2[4], b3[4];
            #pragma unroll
            for (int jj = 0; jj < 4; ++jj) {
                int ii = i0 + g * 4 + jj;
                float xt = sc[PADI(ii)];
                float xo = sc[PADI(ii - 20)];
                w  += xt - xo;                    float ma  = w  * 0.05f;
                wd += xo - sc[PADI(ii - 40)];     float mad = wd * 0.05f;
                float tn = xt - ma;
                float to = xo - mad;
                V += tn * tn - to * to;
                float var = fmaxf(V, 0.f) * 0.05f;
                float sd  = sqrtf(var + FEPS);
                float bbu = ma + 2.f * sd;
                float bbl = ma - 2.f * sd;
                b0[jj] = bbu; b1[jj] = ma; b2[jj] = bbl;
                b3[jj] = __fdividef(xt - bbl, bbu - bbl + FEPS);
            }
            int go = g * 4;
            *(float4*)(ob + 12 * BT + go) = make_float4(b0[0], b0[1], b0[2], b0[3]);
            *(float4*)(ob + 13 * BT + go) = make_float4(b1[0], b1[1], b1[2], b1[3]);
            *(float4*)(ob + 14 * BT + go) = make_float4(b2[0], b2[1], b2[2], b2[3]);
            *(float4*)(ob + 15 * BT + go) = make_float4(b3[0], b3[1], b3[2], b3[3]);
        }
    }
}

extern "C" void kernel_launch(void* const* d_in, const int* in_sizes, int n_in,
                              void* d_out, int out_size)
{
    const float* close = (const float*)d_in[0];
    float* out = (float*)d_out;
    int B = in_sizes[0] / TT;                 // 512
    size_t BT = (size_t)B * TT;
    feat_kernel<<<B * 4, NTH>>>(close, out, BT);
}

// round 6
// speedup vs baseline: 1.1030x; 1.1030x over previous
#include <cuda_runtime.h>

#define TT    8192
#define SEG   2048
#define HALO  256
#define TOT   (SEG + HALO)     // 2304
#define NTH   256
#define CH    8                // emission chunk
#define CHS   9                // scan chunk (TOT/NTH)
#define NW    (NTH/32)
#define FEPS  1e-8f
#define SC_SZ (TOT + TOT/32)   // 2376

__device__ __forceinline__ int PADI(int i){ return i + (i >> 5); }

// inclusive warp scan of affine states: (c,d) == y_out = c*y_in + d
__device__ __forceinline__ void wscan(float& c, float& d, int lane){
    #pragma unroll
    for (int off = 1; off < 32; off <<= 1) {
        float pc = __shfl_up_sync(0xffffffffu, c, off);
        float pd = __shfl_up_sync(0xffffffffu, d, off);
        if (lane >= off) { d = fmaf(pd, c, d); c *= pc; }
    }
}

extern "C" __global__ void __launch_bounds__(NTH, 4)
feat_kernel(const float* __restrict__ gclose, float* __restrict__ gout, size_t BT)
{
    __shared__ float sc[SC_SZ];
    __shared__ float SS[TOT / CH];          // 288 8-chunk sums (halo 0..31, seg 32..287)
    __shared__ float swp[3 * NW];
    __shared__ float si[3 * NTH];

    const int blk  = blockIdx.x;
    const int row  = blk >> 2;
    const int seg  = blk & 3;
    const int tid  = threadIdx.x;
    const int lane = tid & 31;
    const int wid  = tid >> 5;
    const float* x = gclose + (size_t)row * TT;
    const int basem = seg * SEG;

    // ---- fill smem [basem-HALO, basem+SEG), left-pad with x[0] ----
    {
        const float x0 = x[0];
        #pragma unroll
        for (int j = 0; j < 3; ++j) {
            int i4 = tid + j * NTH;
            if (i4 < TOT / 4) {
                int gi = basem - HALO + i4 * 4;
                float4 v = (gi >= 0) ? *(const float4*)(x + gi)
                                     : make_float4(x0, x0, x0, x0);
                int b = i4 * 4;
                sc[PADI(b)]     = v.x;
                sc[PADI(b + 1)] = v.y;
                sc[PADI(b + 2)] = v.z;
                sc[PADI(b + 3)] = v.w;
            }
        }
    }
    __syncthreads();

    const float aF = 2.0f / 13.0f, omF = 1.0f - aF;
    const float aS = 2.0f / 27.0f, omS = 1.0f - aS;
    const float aG = 0.2f,         omG = 0.8f;

    const int i0 = HALO + CH * tid;         // first emitted smem index (8-aligned)
    const int ct = 32 + tid;                // my emission chunk id in SS
    float* ob = gout + (size_t)row * TT + basem + CH * tid;

    // ===== pass A: EMA12/26 affine scan over TOT (CHS=9/thread) + SS fill =====
    float yF0, yS0;
    {
        const int s0 = tid * CHS;
        float cF = 1.f, dF = 0.f, cS = 1.f, dS = 0.f;
        #pragma unroll
        for (int k = 0; k < CHS; ++k) {
            float v = sc[PADI(s0 + k)];
            dF = fmaf(aF, v, omF * dF); cF *= omF;
            dS = fmaf(aS, v, omS * dS); cS *= omS;
        }
        // emission-aligned chunk sums — land before this pass's barrier
        {
            float S = 0.f;
            #pragma unroll 1
            for (int k = 0; k < CH; ++k) S += sc[PADI(i0 + k)];
            SS[ct] = S;
            if (tid < 32) {
                float sh = 0.f;
                #pragma unroll 1
                for (int k = 0; k < CH; ++k) sh += sc[PADI(tid * CH + k)];
                SS[tid] = sh;
            }
        }
        wscan(cF, dF, lane);
        wscan(cS, dS, lane);
        if (lane == 31) { swp[wid] = dF; swp[NW + wid] = dS; }
        float uF  = __shfl_up_sync(0xffffffffu, dF, 1);
        float ucF = __shfl_up_sync(0xffffffffu, cF, 1);
        float uS  = __shfl_up_sync(0xffffffffu, dS, 1);
        float ucS = __shfl_up_sync(0xffffffffu, cS, 1);
        __syncthreads();
        // per-warp decay om^288 < 3e-10 -> previous warp's aggregate suffices
        float pF = (wid > 0) ? swp[wid - 1]      : 0.f;
        float pS = (wid > 0) ? swp[NW + wid - 1] : 0.f;
        yF0 = (lane == 0) ? pF : fmaf(ucF, pF, uF);
        yS0 = (lane == 0) ? pS : fmaf(ucS, pS, uS);
    }

    // ===== pass B: EMA9 over macd (replay from yF0/yS0) =====
    float y90;
    {
        const int s0 = tid * CHS;
        float yF = yF0, yS = yS0, cG = 1.f, dG = 0.f;
        #pragma unroll
        for (int k = 0; k < CHS; ++k) {
            float v = sc[PADI(s0 + k)];
            yF = fmaf(aF, v, omF * yF);
            yS = fmaf(aS, v, omS * yS);
            float m = yF - yS;
            dG = fmaf(aG, m, omG * dG); cG *= omG;
        }
        wscan(cG, dG, lane);
        if (lane == 31) swp[2 * NW + wid] = dG;
        float uG  = __shfl_up_sync(0xffffffffu, dG, 1);
        float ucG = __shfl_up_sync(0xffffffffu, cG, 1);
        __syncthreads();
        float pG = (wid > 0) ? swp[2 * NW + wid - 1] : 0.f;
        y90 = (lane == 0) ? pG : fmaf(ucG, pG, uG);
    }
    si[tid] = yF0; si[NTH + tid] = yS0; si[2 * NTH + tid] = y90;
    __syncthreads();

    // ===== phase C: emit macd(9), signal(10), hist(11) =====
    {
        int c = i0 / CHS;
        int r = i0 - c * CHS;               // 0..8 replay
        float yF = si[c], yS = si[NTH + c], y9 = si[2 * NTH + c];
        int p = c * CHS;
        #pragma unroll 1
        for (int k = 0; k < 9; ++k) {
            if (k >= r) break;
            float v = sc[PADI(p + k)];
            yF = fmaf(aF, v, omF * yF);
            yS = fmaf(aS, v, omS * yS);
            float m = yF - yS;
            y9 = fmaf(aG, m, omG * y9);
        }
        float* om9 = ob + 9  * BT;
        float* osg = ob + 10 * BT;
        float* oh  = ob + 11 * BT;
        #pragma unroll
        for (int g = 0; g < CH / 4; ++g) {
            float mb[4], sb[4], hb[4];
            #pragma unroll
            for (int jj = 0; jj < 4; ++jj) {
                float v = sc[PADI(i0 + g * 4 + jj)];
                yF = fmaf(aF, v, omF * yF);
                yS = fmaf(aS, v, omS * yS);
                float m = yF - yS;
                y9 = fmaf(aG, m, omG * y9);
                mb[jj] = m; sb[jj] = y9; hb[jj] = m - y9;
            }
            *(float4*)(om9 + g * 4) = make_float4(mb[0], mb[1], mb[2], mb[3]);
            *(float4*)(osg + g * 4) = make_float4(sb[0], sb[1], sb[2], sb[3]);
            *(float4*)(oh  + g * 4) = make_float4(hb[0], hb[1], hb[2], hb[3]);
        }
    }

    // ===== phase W: MA5/10/20/50 + ratios (0..7), RSI (8), ATR (16) =====
    float wdB;   // 20-sum ending i0-21 (for Bollinger)
    {
        // register-lean inits: SS sums + a few direct LDS, serial loops
        float s5  = sc[PADI(i0 - 1)] + sc[PADI(i0 - 2)] + sc[PADI(i0 - 3)]
                  + sc[PADI(i0 - 4)] + sc[PADI(i0 - 5)];
        float s10 = SS[ct - 1] + sc[PADI(i0 - 9)] + sc[PADI(i0 - 10)];
        float s20 = SS[ct - 1] + SS[ct - 2]
                  + sc[PADI(i0 - 17)] + sc[PADI(i0 - 18)] + sc[PADI(i0 - 19)] + sc[PADI(i0 - 20)];
        float s50 = SS[ct - 1] + SS[ct - 2] + SS[ct - 3] + SS[ct - 4] + SS[ct - 5] + SS[ct - 6]
                  + sc[PADI(i0 - 49)] + sc[PADI(i0 - 50)];
        wdB = SS[ct - 5] + SS[ct - 4]
            + sc[PADI(i0 - 21)] + sc[PADI(i0 - 22)] + sc[PADI(i0 - 23)] + sc[PADI(i0 - 24)];
        float gs = 0.f, ls = 0.f;
        #pragma unroll 1
        for (int k = 1; k <= 14; ++k) {
            float d = sc[PADI(i0 - k)] - sc[PADI(i0 - k - 1)];
            gs += fmaxf(d, 0.f);
            ls += fmaxf(-d, 0.f);
        }
        float xprev = sc[PADI(i0 - 1)];
        float xm15  = sc[PADI(i0 - 15)];
        #pragma unroll
        for (int g = 0; g < CH / 4; ++g) {
            float a0[4], a1[4], a2[4], a3[4], a4[4], a5v[4], a6[4], a7[4], a8[4], a9[4];
            #pragma unroll
            for (int jj = 0; jj < 4; ++jj) {
                int ii = i0 + g * 4 + jj;
                float xt = sc[PADI(ii)];
                s5  += xt - sc[PADI(ii - 5)];
                s10 += xt - sc[PADI(ii - 10)];
                s20 += xt - sc[PADI(ii - 20)];
                s50 += xt - sc[PADI(ii - 50)];
                float d = xt - xprev;
                gs += fmaxf(d, 0.f);
                ls += fmaxf(-d, 0.f);
                float xm14 = sc[PADI(ii - 14)];
                float dl = xm14 - xm15;
                gs -= fmaxf(dl, 0.f);
                ls -= fmaxf(-dl, 0.f);
                xm15 = xm14; xprev = xt;
                float ma5  = s5  * 0.2f;
                float ma10 = s10 * 0.1f;
                float ma20 = s20 * 0.05f;
                float ma50 = s50 * 0.02f;
                a0[jj] = ma5;  a1[jj]  = __fdividef(xt, ma5  + FEPS);
                a2[jj] = ma10; a3[jj]  = __fdividef(xt, ma10 + FEPS);
                a4[jj] = ma20; a5v[jj] = __fdividef(xt, ma20 + FEPS);
                a6[jj] = ma50; a7[jj]  = __fdividef(xt, ma50 + FEPS);
                a8[jj] = 100.f * __fdividef(gs, gs + ls + 14.f * FEPS);
                a9[jj] = (gs + ls) * (1.f / 14.f);
            }
            int go = g * 4;
            *(float4*)(ob + 0  * BT + go) = make_float4(a0[0], a0[1], a0[2], a0[3]);
            *(float4*)(ob + 1  * BT + go) = make_float4(a1[0], a1[1], a1[2], a1[3]);
            *(float4*)(ob + 2  * BT + go) = make_float4(a2[0], a2[1], a2[2], a2[3]);
            *(float4*)(ob + 3  * BT + go) = make_float4(a3[0], a3[1], a3[2], a3[3]);
            *(float4*)(ob + 4  * BT + go) = make_float4(a4[0], a4[1], a4[2], a4[3]);
            *(float4*)(ob + 5  * BT + go) = make_float4(a5v[0], a5v[1], a5v[2], a5v[3]);
            *(float4*)(ob + 6  * BT + go) = make_float4(a6[0], a6[1], a6[2], a6[3]);
            *(float4*)(ob + 7  * BT + go) = make_float4(a7[0], a7[1], a7[2], a7[3]);
            *(float4*)(ob + 8  * BT + go) = make_float4(a8[0], a8[1], a8[2], a8[3]);
            *(float4*)(ob + 16 * BT + go) = make_float4(a9[0], a9[1], a9[2], a9[3]);
        }
    }

    // ===== phase BB: Bollinger (12,13,14) + %B (15), sliding Σ(x−ma)² =====
    {
        float w = wdB;              // 20-sum ending i0-21
        float V = 0.f;
        #pragma unroll 1
        for (int j = i0 - 20; j <= i0 - 1; ++j) {
            float xv = sc[PADI(j)];
            w += xv - sc[PADI(j - 20)];          // w ends at j
            float ma = w * 0.05f;
            float t = xv - ma;
            V = fmaf(t, t, V);
        }
        float wd = wdB;             // delayed 20-sum tracker
        #pragma unroll
        for (int g = 0; g < CH / 4; ++g) {
            float b0[4], b1[4], b2[4], b3[4];
            #pragma unroll
            for (int jj = 0; jj < 4; ++jj) {
                int ii = i0 + g * 4 + jj;
                float xt = sc[PADI(ii)];
                float xo = sc[PADI(ii - 20)];
                w  += xt - xo;                    float ma  = w  * 0.05f;
                wd += xo - sc[PADI(ii - 40)];     float mad = wd * 0.05f;
                float tn = xt - ma;
                float to = xo - mad;
                V += tn * tn - to * to;
                float var = fmaxf(V, 0.f) * 0.05f;
                float sd  = sqrtf(var + FEPS);
                float bbu = ma + 2.f * sd;
                float bbl = ma - 2.f * sd;
                b0[jj] = bbu; b1[jj] = ma; b2[jj] = bbl;
                b3[jj] = __fdividef(xt - bbl, bbu - bbl + FEPS);
            }
            int go = g * 4;
            *(float4*)(ob + 12 * BT + go) = make_float4(b0[0], b0[1], b0[2], b0[3]);
            *(float4*)(ob + 13 * BT + go) = make_float4(b1[0], b1[1], b1[2], b1[3]);
            *(float4*)(ob + 14 * BT + go) = make_float4(b2[0], b2[1], b2[2], b2[3]);
            *(float4*)(ob + 15 * BT + go) = make_float4(b3[0], b3[1], b3[2], b3[3]);
        }
    }
}

extern "C" void kernel_launch(void* const* d_in, const int* in_sizes, int n_in,
                              void* d_out, int out_size)
{
    const float* close = (const float*)d_in[0];
    float* out = (float*)d_out;
    int B = in_sizes[0] / TT;                 // 512
    size_t BT = (size_t)B * TT;
    feat_kernel<<<B * 4, NTH>>>(close, out, BT);
}